// round 8
// baseline (speedup 1.0000x reference)
#include <cuda_runtime.h>
#include <cuda_fp16.h>
#include <math.h>
#include <stdint.h>

#define HDIM   128
#define BMAX   16384
#define TMAX   2000000

// ---------------- scratch (allocation-free: __device__ globals) ----------------
__device__ int   g_offs[BMAX + 1];
__device__ int   g_segid[TMAX];
__device__ float g_cat [(size_t)BMAX * 256];   // [b][0:128]=v_n  [b][128:256]=s_g
__device__ float g_abuf[(size_t)BMAX * 128];   // a_b = W1 v_n + b1 + b2

// sigmoid via MUFU.TANH
__device__ __forceinline__ float sigt(float x) {
    float t;
    asm("tanh.approx.f32 %0, %1;" : "=f"(t) : "f"(0.5f * x));
    return fmaf(0.5f, t, 0.5f);
}

__device__ __forceinline__ void ldsm4(uint32_t& r0, uint32_t& r1, uint32_t& r2, uint32_t& r3, uint32_t addr) {
    asm volatile("ldmatrix.sync.aligned.m8n8.x4.shared.b16 {%0,%1,%2,%3}, [%4];\n"
                 : "=r"(r0), "=r"(r1), "=r"(r2), "=r"(r3) : "r"(addr));
}

__device__ __forceinline__ void mma16816(float* c, uint32_t a0, uint32_t a1, uint32_t a2, uint32_t a3,
                                         uint32_t b0, uint32_t b1) {
    asm volatile("mma.sync.aligned.m16n8k16.row.col.f32.f16.f16.f32 "
                 "{%0,%1,%2,%3}, {%4,%5,%6,%7}, {%8,%9}, {%0,%1,%2,%3};\n"
                 : "+f"(c[0]), "+f"(c[1]), "+f"(c[2]), "+f"(c[3])
                 : "r"(a0), "r"(a1), "r"(a2), "r"(a3), "r"(b0), "r"(b1));
}

// ---------------- K0: prefix sum of seq_len -> g_offs ----------------
__global__ void scan_kernel(const int* __restrict__ seq, int B) {
    __shared__ int ssum[1024];
    int t = threadIdx.x;
    int C = (B + 1023) >> 10;
    int lo = t * C;
    int hi = min(lo + C, B);
    int s = 0;
    for (int i = lo; i < hi; ++i) s += seq[i];
    ssum[t] = s;
    __syncthreads();
    for (int d = 1; d < 1024; d <<= 1) {
        int v = 0;
        if (t >= d) v = ssum[t - d];
        __syncthreads();
        if (t >= d) ssum[t] += v;
        __syncthreads();
    }
    int run = (t > 0) ? ssum[t - 1] : 0;
    if (t == 0) g_offs[0] = 0;
    for (int i = lo; i < hi; ++i) { run += seq[i]; g_offs[i + 1] = run; }
}

// ---------------- K1: seg ids + v_n gather + zero s_g (merged) ----------------
__global__ void segvn_kernel(const float* __restrict__ intra, const float* __restrict__ inter, int B) {
    int b = blockIdx.x;
    if (b >= B) return;
    int j = threadIdx.x;           // 128 threads
    int s = g_offs[b], e = g_offs[b + 1];
    int last = e - 1;
    float v = 0.0f;
    if (last >= s) {
        size_t idx = (size_t)last * HDIM + j;
        v = fmaxf(intra[idx], inter[idx]);
    }
    g_cat[(size_t)b * 256 + j] = v;
    g_cat[(size_t)b * 256 + 128 + j] = 0.0f;
    for (int i = s + j; i < e; i += 128) g_segid[i] = b;
}

// ---------------- fp16 wmma GEMM (small kernels) ----------------
#include <mma.h>
using namespace nvcuda;
__global__ __launch_bounds__(256, 1)
void gemm_kernel(const float* __restrict__ A, int lda, int K,
                 const float* __restrict__ W,
                 const float* __restrict__ ba, const float* __restrict__ bb,
                 float* __restrict__ C, int M)
{
    extern __shared__ char smraw[];
    const int KS = K + 8;
    half*  Wh = (half*)smraw;
    half*  Ah = Wh + 128 * KS;
    float* Zt = (float*)(Ah + 32 * KS);
    const int tid = threadIdx.x;
    const int w   = tid >> 5;
    const int nf4 = K >> 2;

    for (int u = tid; u < 128 * nf4; u += 256) {
        int n = u / nf4, c4 = u - n * nf4;
        float4 v = *(const float4*)(W + (size_t)n * K + c4 * 4);
        half2* dst = (half2*)(Wh + (size_t)n * KS + c4 * 4);
        dst[0] = __floats2half2_rn(v.x, v.y);
        dst[1] = __floats2half2_rn(v.z, v.w);
    }
    __syncthreads();

    const int m_t = w >> 2;
    const int n0  = (w & 3) * 2;
    const int ntiles = (M + 31) >> 5;

    for (int tile = blockIdx.x; tile < ntiles; tile += gridDim.x) {
        int row0 = tile << 5;
        int rem  = min(32, M - row0);

        for (int u = tid; u < 32 * nf4; u += 256) {
            int r = u / nf4, c4 = u - r * nf4;
            float4 v = make_float4(0.f, 0.f, 0.f, 0.f);
            if (r < rem) v = *(const float4*)(A + (size_t)(row0 + r) * lda + c4 * 4);
            half2* dst = (half2*)(Ah + (size_t)r * KS + c4 * 4);
            dst[0] = __floats2half2_rn(v.x, v.y);
            dst[1] = __floats2half2_rn(v.z, v.w);
        }
        __syncthreads();

        wmma::fragment<wmma::accumulator, 16, 16, 16, float> c0f, c1f;
        wmma::fill_fragment(c0f, 0.0f);
        wmma::fill_fragment(c1f, 0.0f);
        for (int kk = 0; kk < K; kk += 16) {
            wmma::fragment<wmma::matrix_a, 16, 16, 16, half, wmma::row_major> af;
            wmma::load_matrix_sync(af, Ah + m_t * 16 * KS + kk, KS);
            wmma::fragment<wmma::matrix_b, 16, 16, 16, half, wmma::col_major> b0f, b1f;
            wmma::load_matrix_sync(b0f, Wh + (n0 * 16) * KS + kk, KS);
            wmma::load_matrix_sync(b1f, Wh + ((n0 + 1) * 16) * KS + kk, KS);
            wmma::mma_sync(c0f, af, b0f, c0f);
            wmma::mma_sync(c1f, af, b1f, c1f);
        }
        wmma::store_matrix_sync(Zt + m_t * 16 * 136 + n0 * 16,       c0f, 136, wmma::mem_row_major);
        wmma::store_matrix_sync(Zt + m_t * 16 * 136 + (n0 + 1) * 16, c1f, 136, wmma::mem_row_major);
        __syncthreads();

        for (int u = tid; u < 32 * 128; u += 256) {
            int r = u >> 7, n = u & 127;
            if (r < rem) {
                float val = Zt[r * 136 + n] + ba[n];
                if (bb) val += bb[n];
                C[(size_t)(row0 + r) * 128 + n] = val;
            }
        }
        __syncthreads();
    }
}

// ---------------- MAIN: 64-token tiles, double-buffered, (2,4) warp partition ----------------
// smem layout (bytes):
#define AH_STRIDE 17408                     // one Ah buffer: [64][136] f16
#define OFF_AH   0                          // 2 buffers     : 34816
#define OFF_W2H  34816                      // [128][136] f16: 34816
#define OFF_PART (OFF_W2H + 34816)          // [4][64] f32   : 1024
#define OFF_SEGS (OFF_PART + 1024)          // 2 × [64] int  : 512
#define OFF_QSM  (OFF_SEGS + 512)           // [128] f32     : 512
#define MAIN_SMEM (OFF_QSM + 512)

__global__ __launch_bounds__(256, 3)
void main_kernel(const float* __restrict__ intra, const float* __restrict__ inter,
                 const float* __restrict__ W2,
                 const float* __restrict__ qw, const float* __restrict__ qb,
                 const float* __restrict__ abuf, int T, int ntiles)
{
    extern __shared__ char smraw[];
    half*  Ah0  = (half*) (smraw + OFF_AH);      // 2 buffers of [64][136]
    half*  W2h  = (half*) (smraw + OFF_W2H);
    float* part = (float*)(smraw + OFF_PART);    // [4][64]
    int*   seg0 = (int*)  (smraw + OFF_SEGS);    // 2 buffers of [64]
    float* qsm  = (float*)(smraw + OFF_QSM);

    const int tid  = threadIdx.x;
    const int w    = tid >> 5;
    const int lane = tid & 31;

    // stage W2 -> fp16 smem + q -> smem (once per CTA)
    for (int u = tid; u < 128 * 32; u += 256) {
        int n = u >> 5, c4 = u & 31;
        float4 v = *(const float4*)(W2 + (size_t)n * 128 + c4 * 4);
        half2* dst = (half2*)(W2h + n * 136 + c4 * 4);
        dst[0] = __floats2half2_rn(v.x, v.y);
        dst[1] = __floats2half2_rn(v.z, v.w);
    }
    if (tid < 128) qsm[tid] = qw[tid];
    const float qbv = qb[0];
    __syncthreads();

    const int rg = w >> 2;            // 0..1 : 32-row group
    const int cg = w & 3;             // 0..3 : 32-col group

    // ldmatrix per-lane shared addresses
    uint32_t ah_s = (uint32_t)__cvta_generic_to_shared(Ah0);
    uint32_t w2_s = (uint32_t)__cvta_generic_to_shared(W2h);
    const int arow = (lane & 7) + ((lane >> 3) & 1) * 8;
    const int akof = ((lane >> 4) & 1) * 8;
    const uint32_t aoff0 = ah_s + (uint32_t)(((rg * 32 + arow) * 136 + akof) * 2);
    const uint32_t aoff1 = aoff0 + 16 * 136 * 2;
    const int bn   = (lane & 7) + ((lane >> 4) & 1) * 8;
    const int bkof = ((lane >> 3) & 1) * 8;
    const uint32_t boff0 = w2_s + (uint32_t)(((cg * 32 + bn) * 136 + bkof) * 2);
    const uint32_t boff1 = boff0 + 16 * 136 * 2;

    // ---- prologue: prefetch + compress first tile ----
    uint2 ph[8];
    int   psg = 0;
    int tile = blockIdx.x;
    if (tile < ntiles) {
        int row0 = tile << 6;
        int vld  = min(64, T - row0);
        #pragma unroll
        for (int i = 0; i < 8; ++i) {
            int e = tid + i * 256;
            int r = e >> 5, c4 = e & 31;
            float4 za = make_float4(0.f, 0.f, 0.f, 0.f), zb = za;
            if (r < vld) {
                size_t off = (size_t)(row0 + r) * 128 + c4 * 4;
                za = *(const float4*)(intra + off);
                zb = *(const float4*)(inter + off);
            }
            half2 h0 = __floats2half2_rn(fmaxf(za.x, zb.x), fmaxf(za.y, zb.y));
            half2 h1 = __floats2half2_rn(fmaxf(za.z, zb.z), fmaxf(za.w, zb.w));
            ph[i].x = *(uint32_t*)&h0;
            ph[i].y = *(uint32_t*)&h1;
        }
        if (tid < 64) psg = g_segid[min(row0 + tid, T - 1)];
    }

    int bi = 0;
    for (; tile < ntiles; tile += gridDim.x, bi ^= 1) {
        half* Ahb  = Ah0 + bi * (64 * 136);
        int*  segb = seg0 + bi * 64;
        const uint32_t abufo = (uint32_t)(bi * AH_STRIDE);

        // ---- commit: fp16 hidden -> Ahb; segs ----
        #pragma unroll
        for (int i = 0; i < 8; ++i) {
            int e = tid + i * 256;
            int r = e >> 5, c4 = e & 31;
            *(uint2*)(Ahb + r * 136 + c4 * 4) = ph[i];
        }
        if (tid < 64) segb[tid] = psg;
        __syncthreads();   // A: Ahb + segs visible

        // ---- prefetch + compress next tile (hides under mma) ----
        int ntile = tile + gridDim.x;
        if (ntile < ntiles) {
            int row0n = ntile << 6;
            int vldn  = min(64, T - row0n);
            #pragma unroll
            for (int i = 0; i < 8; ++i) {
                int e = tid + i * 256;
                int r = e >> 5, c4 = e & 31;
                float4 za = make_float4(0.f, 0.f, 0.f, 0.f), zb = za;
                if (r < vldn) {
                    size_t off = (size_t)(row0n + r) * 128 + c4 * 4;
                    za = *(const float4*)(intra + off);
                    zb = *(const float4*)(inter + off);
                }
                half2 h0 = __floats2half2_rn(fmaxf(za.x, zb.x), fmaxf(za.y, zb.y));
                half2 h1 = __floats2half2_rn(fmaxf(za.z, zb.z), fmaxf(za.w, zb.w));
                ph[i].x = *(uint32_t*)&h0;
                ph[i].y = *(uint32_t*)&h1;
            }
            if (tid < 64) psg = g_segid[min(row0n + tid, T - 1)];
        }

        // ---- mma: 32 rows × 32 cols per warp ----
        float acc[2][4][4];
        #pragma unroll
        for (int m = 0; m < 2; ++m)
            #pragma unroll
            for (int n = 0; n < 4; ++n)
                #pragma unroll
                for (int j = 0; j < 4; ++j) acc[m][n][j] = 0.0f;
        #pragma unroll
        for (int kk = 0; kk < 128; kk += 16) {
            uint32_t a0, a1, a2, a3, c0, c1, c2, c3;
            ldsm4(a0, a1, a2, a3, abufo + aoff0 + kk * 2);
            ldsm4(c0, c1, c2, c3, abufo + aoff1 + kk * 2);
            uint32_t b0, b1, b2, b3, d0, d1, d2, d3;
            ldsm4(b0, b1, b2, b3, boff0 + kk * 2);
            ldsm4(d0, d1, d2, d3, boff1 + kk * 2);
            mma16816(acc[0][0], a0, a1, a2, a3, b0, b1);
            mma16816(acc[0][1], a0, a1, a2, a3, b2, b3);
            mma16816(acc[0][2], a0, a1, a2, a3, d0, d1);
            mma16816(acc[0][3], a0, a1, a2, a3, d2, d3);
            mma16816(acc[1][0], c0, c1, c2, c3, b0, b1);
            mma16816(acc[1][1], c0, c1, c2, c3, b2, b3);
            mma16816(acc[1][2], c0, c1, c2, c3, d0, d1);
            mma16816(acc[1][3], c0, c1, c2, c3, d2, d3);
        }

        // ---- epilogue: alpha partials for 4 rows per thread ----
        {
            const int r0 = rg * 32 + (lane >> 2);
            const float* ab0 = abuf + (size_t)segb[r0]      * 128;
            const float* ab1 = abuf + (size_t)segb[r0 + 8]  * 128;
            const float* ab2 = abuf + (size_t)segb[r0 + 16] * 128;
            const float* ab3 = abuf + (size_t)segb[r0 + 24] * 128;
            float p0 = 0.0f, p1 = 0.0f, p2 = 0.0f, p3 = 0.0f;
            #pragma unroll
            for (int n2 = 0; n2 < 4; ++n2) {
                const int cb = cg * 32 + n2 * 8 + (lane & 3) * 2;
                float2 q  = *(const float2*)(qsm + cb);
                float2 A0 = __ldg((const float2*)(ab0 + cb));
                float2 A1 = __ldg((const float2*)(ab1 + cb));
                float2 A2 = __ldg((const float2*)(ab2 + cb));
                float2 A3 = __ldg((const float2*)(ab3 + cb));
                p0 += q.x * sigt(acc[0][n2][0] + A0.x) + q.y * sigt(acc[0][n2][1] + A0.y);
                p1 += q.x * sigt(acc[0][n2][2] + A1.x) + q.y * sigt(acc[0][n2][3] + A1.y);
                p2 += q.x * sigt(acc[1][n2][0] + A2.x) + q.y * sigt(acc[1][n2][1] + A2.y);
                p3 += q.x * sigt(acc[1][n2][2] + A3.x) + q.y * sigt(acc[1][n2][3] + A3.y);
            }
            p0 += __shfl_xor_sync(0xffffffffu, p0, 1);
            p0 += __shfl_xor_sync(0xffffffffu, p0, 2);
            p1 += __shfl_xor_sync(0xffffffffu, p1, 1);
            p1 += __shfl_xor_sync(0xffffffffu, p1, 2);
            p2 += __shfl_xor_sync(0xffffffffu, p2, 1);
            p2 += __shfl_xor_sync(0xffffffffu, p2, 2);
            p3 += __shfl_xor_sync(0xffffffffu, p3, 1);
            p3 += __shfl_xor_sync(0xffffffffu, p3, 2);
            if ((lane & 3) == 0) {
                part[cg * 64 + r0]      = p0;
                part[cg * 64 + r0 + 8]  = p1;
                part[cg * 64 + r0 + 16] = p2;
                part[cg * 64 + r0 + 24] = p3;
            }
        }
        __syncthreads();   // C: part visible

        // ---- segment pooling from fp16 Ahb (thread = column pair, 16 rows) ----
        {
            const int j2 = tid & 63;
            const int h  = tid >> 6;
            const int t0 = h * 16;
            float sgx = 0.0f, sgy = 0.0f;
            int cur = segb[t0];
            #pragma unroll 4
            for (int t = t0; t < t0 + 16; ++t) {
                int s = segb[t];
                if (s != cur) {
                    atomicAdd(&g_cat[(size_t)cur * 256 + 128 + 2 * j2],     sgx);
                    atomicAdd(&g_cat[(size_t)cur * 256 + 128 + 2 * j2 + 1], sgy);
                    sgx = sgy = 0.0f;
                    cur = s;
                }
                float al = qbv + part[t] + part[64 + t] + part[128 + t] + part[192 + t];
                half2 hv = *(const half2*)(Ahb + t * 136 + 2 * j2);
                float2 f = __half22float2(hv);
                sgx = fmaf(al, f.x, sgx);
                sgy = fmaf(al, f.y, sgy);
            }
            atomicAdd(&g_cat[(size_t)cur * 256 + 128 + 2 * j2],     sgx);
            atomicAdd(&g_cat[(size_t)cur * 256 + 128 + 2 * j2 + 1], sgy);
        }
        // no tail barrier: next commit writes the other buffer; syncA fences reads
    }
}

// ---------------- launch ----------------
#define GEMM_SMEM(K)  ((160 * ((K) + 8)) * 2 + 32 * 136 * 4)

extern "C" void kernel_launch(void* const* d_in, const int* in_sizes, int n_in,
                              void* d_out, int out_size)
{
    const float* intra = (const float*)d_in[0];
    const float* inter = (const float*)d_in[1];
    const float* W1    = (const float*)d_in[2];
    const float* b1    = (const float*)d_in[3];
    const float* W2    = (const float*)d_in[4];
    const float* b2    = (const float*)d_in[5];
    const float* qw    = (const float*)d_in[6];
    const float* qb    = (const float*)d_in[7];
    const float* W3    = (const float*)d_in[8];
    const float* b3    = (const float*)d_in[9];
    const int*   seq   = (const int*)d_in[10];
    const int B = in_sizes[10];
    const int T = in_sizes[0] / HDIM;
    const int ntiles = (T + 63) >> 6;
    const int gtiles = (B + 31) >> 5;

    cudaFuncSetAttribute(main_kernel, cudaFuncAttributeMaxDynamicSharedMemorySize, MAIN_SMEM);
    cudaFuncSetAttribute(gemm_kernel, cudaFuncAttributeMaxDynamicSharedMemorySize, GEMM_SMEM(256));

    float *catp = nullptr, *abufp = nullptr;
    cudaGetSymbolAddress((void**)&catp,  g_cat);
    cudaGetSymbolAddress((void**)&abufp, g_abuf);

    scan_kernel<<<1, 1024>>>(seq, B);
    segvn_kernel<<<B, 128>>>(intra, inter, B);
    gemm_kernel<<<gtiles, 256, GEMM_SMEM(128)>>>(catp, 256, 128, W1, b1, b2, abufp, B);
    main_kernel<<<444, 256, MAIN_SMEM>>>(intra, inter, W2, qw, qb, abufp, T, ntiles);
    gemm_kernel<<<gtiles, 256, GEMM_SMEM(256)>>>(catp, 256, 256, W3, b3, nullptr, (float*)d_out, B);
}

// round 10
// speedup vs baseline: 1.1683x; 1.1683x over previous
#include <cuda_runtime.h>
#include <cuda_fp16.h>
#include <math.h>
#include <stdint.h>

#define HDIM   128
#define BMAX   16384
#define TMAX   2000000

// ---------------- scratch (allocation-free: __device__ globals) ----------------
__device__ int   g_offs[BMAX + 1];
__device__ int   g_segid[TMAX];
__device__ float g_cat [(size_t)BMAX * 256];   // [b][0:128]=v_n  [b][128:256]=s_g
__device__ float g_abuf[(size_t)BMAX * 128];   // a_b = W1 v_n + b1 + b2

// sigmoid via MUFU.TANH
__device__ __forceinline__ float sigt(float x) {
    float t;
    asm("tanh.approx.f32 %0, %1;" : "=f"(t) : "f"(0.5f * x));
    return fmaf(0.5f, t, 0.5f);
}

__device__ __forceinline__ void ldsm4(uint32_t& r0, uint32_t& r1, uint32_t& r2, uint32_t& r3, uint32_t addr) {
    asm volatile("ldmatrix.sync.aligned.m8n8.x4.shared.b16 {%0,%1,%2,%3}, [%4];\n"
                 : "=r"(r0), "=r"(r1), "=r"(r2), "=r"(r3) : "r"(addr));
}

__device__ __forceinline__ void mma16816(float* c, uint32_t a0, uint32_t a1, uint32_t a2, uint32_t a3,
                                         uint32_t b0, uint32_t b1) {
    asm volatile("mma.sync.aligned.m16n8k16.row.col.f32.f16.f16.f32 "
                 "{%0,%1,%2,%3}, {%4,%5,%6,%7}, {%8,%9}, {%0,%1,%2,%3};\n"
                 : "+f"(c[0]), "+f"(c[1]), "+f"(c[2]), "+f"(c[3])
                 : "r"(a0), "r"(a1), "r"(a2), "r"(a3), "r"(b0), "r"(b1));
}

// ---------------- K0: prefix sum of seq_len -> g_offs ----------------
__global__ void scan_kernel(const int* __restrict__ seq, int B) {
    __shared__ int ssum[1024];
    int t = threadIdx.x;
    int C = (B + 1023) >> 10;
    int lo = t * C;
    int hi = min(lo + C, B);
    int s = 0;
    for (int i = lo; i < hi; ++i) s += seq[i];
    ssum[t] = s;
    __syncthreads();
    for (int d = 1; d < 1024; d <<= 1) {
        int v = 0;
        if (t >= d) v = ssum[t - d];
        __syncthreads();
        if (t >= d) ssum[t] += v;
        __syncthreads();
    }
    int run = (t > 0) ? ssum[t - 1] : 0;
    if (t == 0) g_offs[0] = 0;
    for (int i = lo; i < hi; ++i) { run += seq[i]; g_offs[i + 1] = run; }
}

// ---------------- K1: seg ids + v_n gather + zero s_g (merged) ----------------
__global__ void segvn_kernel(const float* __restrict__ intra, const float* __restrict__ inter, int B) {
    int b = blockIdx.x;
    if (b >= B) return;
    int j = threadIdx.x;           // 128 threads
    int s = g_offs[b], e = g_offs[b + 1];
    int last = e - 1;
    float v = 0.0f;
    if (last >= s) {
        size_t idx = (size_t)last * HDIM + j;
        v = fmaxf(intra[idx], inter[idx]);
    }
    g_cat[(size_t)b * 256 + j] = v;
    g_cat[(size_t)b * 256 + 128 + j] = 0.0f;
    for (int i = s + j; i < e; i += 128) g_segid[i] = b;
}

// ---------------- fp16 wmma GEMM (small kernels) ----------------
#include <mma.h>
using namespace nvcuda;
__global__ __launch_bounds__(256, 1)
void gemm_kernel(const float* __restrict__ A, int lda, int K,
                 const float* __restrict__ W,
                 const float* __restrict__ ba, const float* __restrict__ bb,
                 float* __restrict__ C, int M)
{
    extern __shared__ char smraw[];
    const int KS = K + 8;
    half*  Wh = (half*)smraw;
    half*  Ah = Wh + 128 * KS;
    float* Zt = (float*)(Ah + 32 * KS);
    const int tid = threadIdx.x;
    const int w   = tid >> 5;
    const int nf4 = K >> 2;

    for (int u = tid; u < 128 * nf4; u += 256) {
        int n = u / nf4, c4 = u - n * nf4;
        float4 v = *(const float4*)(W + (size_t)n * K + c4 * 4);
        half2* dst = (half2*)(Wh + (size_t)n * KS + c4 * 4);
        dst[0] = __floats2half2_rn(v.x, v.y);
        dst[1] = __floats2half2_rn(v.z, v.w);
    }
    __syncthreads();

    const int m_t = w >> 2;
    const int n0  = (w & 3) * 2;
    const int ntiles = (M + 31) >> 5;

    for (int tile = blockIdx.x; tile < ntiles; tile += gridDim.x) {
        int row0 = tile << 5;
        int rem  = min(32, M - row0);

        for (int u = tid; u < 32 * nf4; u += 256) {
            int r = u / nf4, c4 = u - r * nf4;
            float4 v = make_float4(0.f, 0.f, 0.f, 0.f);
            if (r < rem) v = *(const float4*)(A + (size_t)(row0 + r) * lda + c4 * 4);
            half2* dst = (half2*)(Ah + (size_t)r * KS + c4 * 4);
            dst[0] = __floats2half2_rn(v.x, v.y);
            dst[1] = __floats2half2_rn(v.z, v.w);
        }
        __syncthreads();

        wmma::fragment<wmma::accumulator, 16, 16, 16, float> c0f, c1f;
        wmma::fill_fragment(c0f, 0.0f);
        wmma::fill_fragment(c1f, 0.0f);
        for (int kk = 0; kk < K; kk += 16) {
            wmma::fragment<wmma::matrix_a, 16, 16, 16, half, wmma::row_major> af;
            wmma::load_matrix_sync(af, Ah + m_t * 16 * KS + kk, KS);
            wmma::fragment<wmma::matrix_b, 16, 16, 16, half, wmma::col_major> b0f, b1f;
            wmma::load_matrix_sync(b0f, Wh + (n0 * 16) * KS + kk, KS);
            wmma::load_matrix_sync(b1f, Wh + ((n0 + 1) * 16) * KS + kk, KS);
            wmma::mma_sync(c0f, af, b0f, c0f);
            wmma::mma_sync(c1f, af, b1f, c1f);
        }
        wmma::store_matrix_sync(Zt + m_t * 16 * 136 + n0 * 16,       c0f, 136, wmma::mem_row_major);
        wmma::store_matrix_sync(Zt + m_t * 16 * 136 + (n0 + 1) * 16, c1f, 136, wmma::mem_row_major);
        __syncthreads();

        for (int u = tid; u < 32 * 128; u += 256) {
            int r = u >> 7, n = u & 127;
            if (r < rem) {
                float val = Zt[r * 136 + n] + ba[n];
                if (bb) val += bb[n];
                C[(size_t)(row0 + r) * 128 + n] = val;
            }
        }
        __syncthreads();
    }
}

// ---------------- MAIN: 64-token tiles, 256 threads, 3 CTAs/SM (round-6 structure) ----------------
// smem layout (bytes):
#define OFF_AH   0                          // [64][136] f16 : 17408
#define OFF_W2H  17408                      // [128][136] f16: 34816
#define OFF_PART (OFF_W2H + 34816)          // [2][64] f32   : 512
#define OFF_SEGS (OFF_PART + 512)           // [64] int      : 256
#define OFF_QSM  (OFF_SEGS + 256)           // [128] f32     : 512
#define MAIN_SMEM (OFF_QSM + 512)

__global__ __launch_bounds__(256, 3)
void main_kernel(const float* __restrict__ intra, const float* __restrict__ inter,
                 const float* __restrict__ W2,
                 const float* __restrict__ qw, const float* __restrict__ qb,
                 const float* __restrict__ abuf, int T, int ntiles)
{
    extern __shared__ char smraw[];
    half*  Ah   = (half*) (smraw + OFF_AH);
    half*  W2h  = (half*) (smraw + OFF_W2H);
    float* part = (float*)(smraw + OFF_PART);    // [2][64]
    int*   segs = (int*)  (smraw + OFF_SEGS);
    float* qsm  = (float*)(smraw + OFF_QSM);

    const int tid  = threadIdx.x;
    const int w    = tid >> 5;
    const int lane = tid & 31;

    // stage W2 -> fp16 smem + q -> smem (once per CTA)
    for (int u = tid; u < 128 * 32; u += 256) {
        int n = u >> 5, c4 = u & 31;
        float4 v = *(const float4*)(W2 + (size_t)n * 128 + c4 * 4);
        half2* dst = (half2*)(W2h + n * 136 + c4 * 4);
        dst[0] = __floats2half2_rn(v.x, v.y);
        dst[1] = __floats2half2_rn(v.z, v.w);
    }
    if (tid < 128) qsm[tid] = qw[tid];
    const float qbv = qb[0];
    __syncthreads();

    const int m_t = w >> 1;           // 0..3 : 16-row m-tile within 64
    const int m0  = m_t * 16;
    const int nh  = w & 1;            // 0/1 : 64-col half

    // ldmatrix per-lane shared addresses
    uint32_t ah_s = (uint32_t)__cvta_generic_to_shared(Ah);
    uint32_t w2_s = (uint32_t)__cvta_generic_to_shared(W2h);
    const int arow = (lane & 7) + ((lane >> 3) & 1) * 8;
    const int akof = ((lane >> 4) & 1) * 8;
    const uint32_t aaddr = ah_s + (uint32_t)(((m0 + arow) * 136 + akof) * 2);
    const int bn   = (lane & 7) + ((lane >> 4) & 1) * 8;
    const int bkof = ((lane >> 3) & 1) * 8;
    uint32_t baddr[4];
    #pragma unroll
    for (int p = 0; p < 4; ++p)
        baddr[p] = w2_s + (uint32_t)(((nh * 64 + p * 16 + bn) * 136 + bkof) * 2);

    // ---- prologue: prefetch + compress first tile ----
    uint2 ph[8];                 // fp16 hidden, 16 regs
    int   psg = 0;
    int tile = blockIdx.x;
    if (tile < ntiles) {
        int row0 = tile << 6;
        int vld  = min(64, T - row0);
        #pragma unroll
        for (int i = 0; i < 8; ++i) {
            int e = tid + i * 256;
            int r = e >> 5, c4 = e & 31;
            float4 za = make_float4(0.f, 0.f, 0.f, 0.f), zb = za;
            if (r < vld) {
                size_t off = (size_t)(row0 + r) * 128 + c4 * 4;
                za = *(const float4*)(intra + off);
                zb = *(const float4*)(inter + off);
            }
            half2 h0 = __floats2half2_rn(fmaxf(za.x, zb.x), fmaxf(za.y, zb.y));
            half2 h1 = __floats2half2_rn(fmaxf(za.z, zb.z), fmaxf(za.w, zb.w));
            ph[i].x = *(uint32_t*)&h0;
            ph[i].y = *(uint32_t*)&h1;
        }
        if (tid < 64) psg = g_segid[min(row0 + tid, T - 1)];
    }

    for (; tile < ntiles; tile += gridDim.x) {
        // ---- commit: fp16 hidden -> Ah; segs ----
        #pragma unroll
        for (int i = 0; i < 8; ++i) {
            int e = tid + i * 256;
            int r = e >> 5, c4 = e & 31;
            *(uint2*)(Ah + r * 136 + c4 * 4) = ph[i];
        }
        if (tid < 64) segs[tid] = psg;
        __syncthreads();   // A

        // ---- prefetch + compress next tile (hides under mma) ----
        int ntile = tile + gridDim.x;
        if (ntile < ntiles) {
            int row0n = ntile << 6;
            int vldn  = min(64, T - row0n);
            #pragma unroll
            for (int i = 0; i < 8; ++i) {
                int e = tid + i * 256;
                int r = e >> 5, c4 = e & 31;
                float4 za = make_float4(0.f, 0.f, 0.f, 0.f), zb = za;
                if (r < vldn) {
                    size_t off = (size_t)(row0n + r) * 128 + c4 * 4;
                    za = *(const float4*)(intra + off);
                    zb = *(const float4*)(inter + off);
                }
                half2 h0 = __floats2half2_rn(fmaxf(za.x, zb.x), fmaxf(za.y, zb.y));
                half2 h1 = __floats2half2_rn(fmaxf(za.z, zb.z), fmaxf(za.w, zb.w));
                ph[i].x = *(uint32_t*)&h0;
                ph[i].y = *(uint32_t*)&h1;
            }
            if (tid < 64) psg = g_segid[min(row0n + tid, T - 1)];
        }

        // ---- mma: Z = hidden @ W2^T (fp16, fp32 acc, in registers) ----
        float acc[8][4];
        #pragma unroll
        for (int n = 0; n < 8; ++n)
            #pragma unroll
            for (int j = 0; j < 4; ++j) acc[n][j] = 0.0f;
        #pragma unroll
        for (int kk = 0; kk < 128; kk += 16) {
            uint32_t a0, a1, a2, a3;
            ldsm4(a0, a1, a2, a3, aaddr + kk * 2);
            #pragma unroll
            for (int p = 0; p < 4; ++p) {
                uint32_t b0, b1, b2, b3;
                ldsm4(b0, b1, b2, b3, baddr[p] + kk * 2);
                mma16816(acc[2 * p],     a0, a1, a2, a3, b0, b1);
                mma16816(acc[2 * p + 1], a0, a1, a2, a3, b2, b3);
            }
        }

        // ---- epilogue: alpha partials from register fragments ----
        {
            const int r0 = m0 + (lane >> 2);
            const int r1 = r0 + 8;
            const float* ab0 = abuf + (size_t)segs[r0] * 128;
            const float* ab1 = abuf + (size_t)segs[r1] * 128;
            float p0 = 0.0f, p1 = 0.0f;
            #pragma unroll
            for (int p = 0; p < 4; ++p) {
                #pragma unroll
                for (int h = 0; h < 2; ++h) {
                    const int cb = nh * 64 + p * 16 + h * 8 + (lane & 3) * 2;
                    const float* F = acc[2 * p + h];
                    float  q0 = qsm[cb], q1 = qsm[cb + 1];
                    float2 av = __ldg((const float2*)(ab0 + cb));
                    float2 cv = __ldg((const float2*)(ab1 + cb));
                    p0 += q0 * sigt(F[0] + av.x) + q1 * sigt(F[1] + av.y);
                    p1 += q0 * sigt(F[2] + cv.x) + q1 * sigt(F[3] + cv.y);
                }
            }
            p0 += __shfl_xor_sync(0xffffffffu, p0, 1);
            p0 += __shfl_xor_sync(0xffffffffu, p0, 2);
            p1 += __shfl_xor_sync(0xffffffffu, p1, 1);
            p1 += __shfl_xor_sync(0xffffffffu, p1, 2);
            if ((lane & 3) == 0) {
                part[nh * 64 + r0] = p0;
                part[nh * 64 + r1] = p1;
            }
        }
        __syncthreads();   // C

        // ---- segment pooling from fp16 Ah (thread = column pair, 16 rows) ----
        {
            const int j2 = tid & 63;        // half2 column index
            const int h  = tid >> 6;        // 0..3
            const int t0 = h * 16;
            float sgx = 0.0f, sgy = 0.0f;
            int cur = segs[t0];
            #pragma unroll 4
            for (int t = t0; t < t0 + 16; ++t) {
                int s = segs[t];
                if (s != cur) {
                    atomicAdd(&g_cat[(size_t)cur * 256 + 128 + 2 * j2],     sgx);
                    atomicAdd(&g_cat[(size_t)cur * 256 + 128 + 2 * j2 + 1], sgy);
                    sgx = sgy = 0.0f;
                    cur = s;
                }
                float al = qbv + part[t] + part[64 + t];
                half2 hv = *(const half2*)(Ah + t * 136 + 2 * j2);
                float2 f = __half22float2(hv);
                sgx = fmaf(al, f.x, sgx);
                sgy = fmaf(al, f.y, sgy);
            }
            atomicAdd(&g_cat[(size_t)cur * 256 + 128 + 2 * j2],     sgx);
            atomicAdd(&g_cat[(size_t)cur * 256 + 128 + 2 * j2 + 1], sgy);
        }
        __syncthreads();   // E (protect Ah/segs/part before next commit)
    }
}

// ---------------- launch ----------------
#define GEMM_SMEM(K)  ((160 * ((K) + 8)) * 2 + 32 * 136 * 4)

extern "C" void kernel_launch(void* const* d_in, const int* in_sizes, int n_in,
                              void* d_out, int out_size)
{
    const float* intra = (const float*)d_in[0];
    const float* inter = (const float*)d_in[1];
    const float* W1    = (const float*)d_in[2];
    const float* b1    = (const float*)d_in[3];
    const float* W2    = (const float*)d_in[4];
    const float* b2    = (const float*)d_in[5];
    const float* qw    = (const float*)d_in[6];
    const float* qb    = (const float*)d_in[7];
    const float* W3    = (const float*)d_in[8];
    const float* b3    = (const float*)d_in[9];
    const int*   seq   = (const int*)d_in[10];
    const int B = in_sizes[10];
    const int T = in_sizes[0] / HDIM;
    const int ntiles = (T + 63) >> 6;
    const int gtiles = (B + 31) >> 5;

    cudaFuncSetAttribute(main_kernel, cudaFuncAttributeMaxDynamicSharedMemorySize, MAIN_SMEM);
    cudaFuncSetAttribute(gemm_kernel, cudaFuncAttributeMaxDynamicSharedMemorySize, GEMM_SMEM(256));

    float *catp = nullptr, *abufp = nullptr;
    cudaGetSymbolAddress((void**)&catp,  g_cat);
    cudaGetSymbolAddress((void**)&abufp, g_abuf);

    scan_kernel<<<1, 1024>>>(seq, B);
    segvn_kernel<<<B, 128>>>(intra, inter, B);
    gemm_kernel<<<gtiles, 256, GEMM_SMEM(128)>>>(catp, 256, 128, W1, b1, b2, abufp, B);
    main_kernel<<<444, 256, MAIN_SMEM>>>(intra, inter, W2, qw, qb, abufp, T, ntiles);
    gemm_kernel<<<gtiles, 256, GEMM_SMEM(256)>>>(catp, 256, 256, W3, b3, nullptr, (float*)d_out, B);
}